// round 9
// baseline (speedup 1.0000x reference)
#include <cuda_runtime.h>
#include <cuda_bf16.h>
#include <cstdint>

// ============================================================================
// Density_Block via bf16 mma.sync m16n8k16, split-precision (3 products).
// out[i] = lerp of softmax(x[i,:] @ W + b) at data-dependent cols L/U.
// N=524288, IND=128, OUTD=256.
// Persistent: W (hi/lo bf16, XOR-swizzled, packed) in smem once; 12 warps/SM.
// Full-stripe cp.async prefetch: each warp copies its NEXT 16-row stripe (8KB
// raw fp32) into a private smem buffer one iteration ahead -> stripe start is
// LDS-only (no exposed DRAM latency).
// ============================================================================

#define IND    128
#define OUTD   256
#define NTHR   384
#define NWARP  (NTHR / 32)

#define SM_WHI  0
#define SM_WLO  65536                      // 128 rows x 512 B each
#define SM_BIAS 131072
#define SM_PF   132096                     // 12 warps x 8 KB
#define SM_TOTAL (SM_PF + NWARP * 8192)    // 230400

#define LOG2E 1.4426950408889634f

__device__ __forceinline__ uint32_t smem_u32(const void* p) {
    uint32_t a;
    asm("{ .reg .u64 t; cvta.to.shared.u64 t, %1; cvt.u32.u64 %0, t; }"
        : "=r"(a) : "l"(p));
    return a;
}

__device__ __forceinline__ float ex2f(float v) {
    float r;
    asm("ex2.approx.f32 %0, %1;" : "=f"(r) : "f"(v));
    return r;
}

__device__ __forceinline__ void cp_async16(uint32_t dst, const void* src) {
    asm volatile("cp.async.ca.shared.global [%0], [%1], 16;"
                 :: "r"(dst), "l"(src) : "memory");
}
__device__ __forceinline__ void cp_commit() {
    asm volatile("cp.async.commit_group;" ::: "memory");
}
__device__ __forceinline__ void cp_wait0() {
    asm volatile("cp.async.wait_group 0;" ::: "memory");
}

__device__ __forceinline__ void ldsm4t(uint32_t& r0, uint32_t& r1,
                                       uint32_t& r2, uint32_t& r3, uint32_t addr) {
    asm volatile("ldmatrix.sync.aligned.m8n8.x4.trans.shared.b16 {%0,%1,%2,%3}, [%4];"
                 : "=r"(r0), "=r"(r1), "=r"(r2), "=r"(r3) : "r"(addr));
}

__device__ __forceinline__ void mma16816(float* d, const uint32_t* a,
                                         uint32_t b0, uint32_t b1) {
    asm volatile("mma.sync.aligned.m16n8k16.row.col.f32.bf16.bf16.f32 "
                 "{%0,%1,%2,%3}, {%4,%5,%6,%7}, {%8,%9}, {%0,%1,%2,%3};"
                 : "+f"(d[0]), "+f"(d[1]), "+f"(d[2]), "+f"(d[3])
                 : "r"(a[0]), "r"(a[1]), "r"(a[2]), "r"(a[3]), "r"(b0), "r"(b1));
}

// W layout: row k (512 B), 16B chunk index c (= n>>3) stored at chunk c ^ (k&7).
__device__ __forceinline__ uint32_t woff(int k, int n) {
    return (uint32_t)(k * 512 + ((((n >> 3) ^ (k & 7)) << 4)) + ((n & 7) << 1));
}

// prefetch full stripe s (16 rows x 512 B) into this warp's buffer
// (rotation swizzle: +row*32 bytes, mod 512)
__device__ __forceinline__ void pf_issue(const float* __restrict__ x, int s,
                                         uint32_t buf, int lane) {
    const float* src = x + ((size_t)s << 4) * IND;
    #pragma unroll
    for (int r = 0; r < 16; r++) {
        const uint32_t off = (uint32_t)r * 512 + (((uint32_t)lane * 16 + r * 32) & 511);
        cp_async16(buf + off, src + r * IND + lane * 4);
    }
    cp_commit();
}

__global__ void __launch_bounds__(NTHR, 1)
density_mma(const float* __restrict__ t, const float* __restrict__ x,
            const float* __restrict__ w, const float* __restrict__ bias,
            float* __restrict__ out, int nstripes)
{
    extern __shared__ __align__(1024) unsigned char smem[];
    float* bs = reinterpret_cast<float*>(smem + SM_BIAS);   // bias * log2e

    const int tid = threadIdx.x;

    // ---- one-time: stage W as (hi, lo) bf16, XOR-swizzled + scaled bias ----
    for (int e = tid; e < IND * OUTD; e += NTHR) {
        const int k = e >> 8, n = e & 255;
        const float v = w[e];
        const __nv_bfloat16 h = __float2bfloat16(v);
        const __nv_bfloat16 l = __float2bfloat16(v - __bfloat162float(h));
        const uint32_t off = woff(k, n);
        *reinterpret_cast<__nv_bfloat16*>(smem + SM_WHI + off) = h;
        *reinterpret_cast<__nv_bfloat16*>(smem + SM_WLO + off) = l;
    }
    if (tid < OUTD) bs[tid] = bias[tid] * LOG2E;
    __syncthreads();

    const int lane = tid & 31;
    const int gq   = lane >> 2;   // 0..7: row within stripe half
    const int qid  = lane & 3;    // 0..3: column quad
    const int gwarp  = blockIdx.x * NWARP + (tid >> 5);
    const int nwarps = gridDim.x * NWARP;

    const uint32_t whi_u = smem_u32(smem) + SM_WHI;
    const uint32_t wlo_u = smem_u32(smem) + SM_WLO;
    const uint32_t buf   = smem_u32(smem) + SM_PF + ((uint32_t)(tid >> 5) << 13);

    // ldmatrix lane addressing for XOR-swizzled W
    const uint32_t r512 = (uint32_t)(lane & 15) * 512;   // row within 16-row k block
    const uint32_t hsel = (uint32_t)(lane >> 4);          // col-chunk select (0/1)
    const uint32_t xm   = (uint32_t)(lane & 7);           // per-lane XOR mask

    if (gwarp < nstripes) pf_issue(x, gwarp, buf, lane);   // prime the pipeline

    for (int s = gwarp; s < nstripes; s += nwarps) {
        const int row0  = s << 4;
        const int row_a = row0 + gq;
        const int row_b = row_a + 8;

        // ---- consume prefetched stripe: LDS + convert into mma fragments ----
        cp_wait0();
        __syncwarp();
        uint32_t Ah[8][4], Al[8][4];
        #pragma unroll
        for (int ks = 0; ks < 8; ks++)
            #pragma unroll
            for (int q = 0; q < 2; q++)
                #pragma unroll
                for (int p = 0; p < 2; p++) {
                    const uint32_t row  = (uint32_t)(p * 8 + gq);
                    const uint32_t byte = (uint32_t)(ks * 64 + qid * 8 + q * 32);
                    const uint32_t off  = row * 512 + ((byte + row * 32) & 511);
                    float2 v;
                    asm volatile("ld.shared.v2.f32 {%0,%1}, [%2];"
                                 : "=f"(v.x), "=f"(v.y) : "r"(buf + off));
                    const __nv_bfloat162 h = __floats2bfloat162_rn(v.x, v.y);
                    const float2 hf = __bfloat1622float2(h);
                    const __nv_bfloat162 l = __floats2bfloat162_rn(v.x - hf.x, v.y - hf.y);
                    Ah[ks][q * 2 + p] = *reinterpret_cast<const uint32_t*>(&h);
                    Al[ks][q * 2 + p] = *reinterpret_cast<const uint32_t*>(&l);
                }
        __syncwarp();   // all lanes done reading buf before refilling it

        // ---- prefetch next stripe (lands during the MMA loop) ----
        const int nxt = s + nwarps;
        if (nxt < nstripes) pf_issue(x, nxt, buf, lane);

        // ---- per-row grid indices / softmax state ----
        const float ta = __ldg(t + row_a), tb = __ldg(t + row_b);
        const float tga = ta * 255.0f, tgb = tb * 255.0f;
        const float Uaf = ceilf(tga),  Ubf = ceilf(tgb);
        const float intera = 1.0f - (Uaf - tga);
        const float interb = 1.0f - (Ubf - tgb);
        const int Uia = (int)Uaf, Uib = (int)Ubf;
        const int Lia = max(Uia - 1, 0), Lib = max(Uib - 1, 0);

        float sa = 0.f, sb = 0.f, gla = 0.f, glb = 0.f, gua = 0.f, gub = 0.f;

        // ---- 8 column chunks of 32 (rolled loop: small I$ footprint) ----
        for (int c = 0; c < 8; c++) {
            float acc[4][4];
            #pragma unroll
            for (int i = 0; i < 4; i++)
                #pragma unroll
                for (int j = 0; j < 4; j++) acc[i][j] = 0.f;

            const uint32_t c4 = (uint32_t)(c * 4) + hsel;
            const uint32_t u0 = ((c4)     ^ xm) << 4;
            const uint32_t u1 = ((c4 + 2) ^ xm) << 4;

            #pragma unroll
            for (int ks = 0; ks < 8; ks++) {
                const uint32_t base = (uint32_t)ks * 8192 + r512;
                uint32_t h0, h1, h2, h3, h4, h5, h6, h7;
                uint32_t l0, l1, l2, l3, l4, l5, l6, l7;
                ldsm4t(h0, h1, h2, h3, whi_u + base + u0);
                ldsm4t(h4, h5, h6, h7, whi_u + base + u1);
                ldsm4t(l0, l1, l2, l3, wlo_u + base + u0);
                ldsm4t(l4, l5, l6, l7, wlo_u + base + u1);
                // phase 1: hi*hi (4 independent accs)
                mma16816(acc[0], Ah[ks], h0, h1);
                mma16816(acc[1], Ah[ks], h2, h3);
                mma16816(acc[2], Ah[ks], h4, h5);
                mma16816(acc[3], Ah[ks], h6, h7);
                // phase 2: hi*lo
                mma16816(acc[0], Ah[ks], l0, l1);
                mma16816(acc[1], Ah[ks], l2, l3);
                mma16816(acc[2], Ah[ks], l4, l5);
                mma16816(acc[3], Ah[ks], l6, l7);
                // phase 3: lo*hi
                mma16816(acc[0], Al[ks], h0, h1);
                mma16816(acc[1], Al[ks], h2, h3);
                mma16816(acc[2], Al[ks], h4, h5);
                mma16816(acc[3], Al[ks], h6, h7);
            }

            // ---- chunk epilogue: exp2(acc*log2e + b2) + sum + one-hot gather ----
            #pragma unroll
            for (int nt = 0; nt < 4; nt++) {
                const int col = c * 32 + nt * 8 + qid * 2;
                const float b0 = bs[col], b1 = bs[col + 1];
                const float e0 = ex2f(fmaf(acc[nt][0], LOG2E, b0));
                const float e1 = ex2f(fmaf(acc[nt][1], LOG2E, b1));
                const float e2 = ex2f(fmaf(acc[nt][2], LOG2E, b0));
                const float e3 = ex2f(fmaf(acc[nt][3], LOG2E, b1));
                sa += e0 + e1;
                sb += e2 + e3;
                if (col == Lia)     gla = e0;
                if (col + 1 == Lia) gla = e1;
                if (col == Uia)     gua = e0;
                if (col + 1 == Uia) gua = e1;
                if (col == Lib)     glb = e2;
                if (col + 1 == Lib) glb = e3;
                if (col == Uib)     gub = e2;
                if (col + 1 == Uib) gub = e3;
            }
        }

        // ---- reduce across the 4-thread column quad ----
        #pragma unroll
        for (int d = 1; d < 4; d <<= 1) {
            sa  += __shfl_xor_sync(0xffffffffu, sa,  d);
            sb  += __shfl_xor_sync(0xffffffffu, sb,  d);
            gla += __shfl_xor_sync(0xffffffffu, gla, d);
            gua += __shfl_xor_sync(0xffffffffu, gua, d);
            glb += __shfl_xor_sync(0xffffffffu, glb, d);
            gub += __shfl_xor_sync(0xffffffffu, gub, d);
        }
        if (qid == 0) {
            out[row_a] = __fdividef(gla + (gua - gla) * intera, sa);
            out[row_b] = __fdividef(glb + (gub - glb) * interb, sb);
        }
    }
}

extern "C" void kernel_launch(void* const* d_in, const int* in_sizes, int n_in,
                              void* d_out, int out_size)
{
    const float* t    = (const float*)d_in[0];
    const float* x    = (const float*)d_in[1];
    const float* w    = (const float*)d_in[2];
    const float* bias = (const float*)d_in[3];
    float* out        = (float*)d_out;

    const int n        = in_sizes[0];
    const int nstripes = n >> 4;       // 32768

    int dev = 0, smc = 0;
    cudaGetDevice(&dev);
    cudaDeviceGetAttribute(&smc, cudaDevAttrMultiProcessorCount, dev);
    if (smc <= 0) smc = 148;

    cudaFuncSetAttribute(density_mma,
                         cudaFuncAttributeMaxDynamicSharedMemorySize, SM_TOTAL);
    density_mma<<<smc, NTHR, SM_TOTAL>>>(t, x, w, bias, out, nstripes);
}

// round 10
// speedup vs baseline: 1.0323x; 1.0323x over previous
#include <cuda_runtime.h>
#include <cuda_bf16.h>
#include <cstdint>

// ============================================================================
// Density_Block via bf16 mma.sync m16n8k16, split-precision (3 products).
// out[i] = lerp of softmax(x[i,:] @ W + b) at data-dependent cols L/U.
// N=524288, IND=128, OUTD=256.
// Persistent: W (hi/lo bf16) in smem once; 16 warps/SM stream 16-row stripes.
// NEW: dynamic stripe assignment via global atomic ticket (removes the
// 13-vs-14 stripes/warp tail imbalance and desynchronizes warp phases).
// ============================================================================

#define IND    128
#define OUTD   256
#define WPITCH 264      // padded bf16 pitch: 528B row stride -> conflict-free ldmatrix
#define NTHR   512

#define SM_WHI  0
#define SM_WLO  (IND * WPITCH * 2)          // 67584
#define SM_BIAS (2 * IND * WPITCH * 2)      // 135168
#define SM_TOTAL (SM_BIAS + OUTD * 4 + 16)

#define LOG2E 1.4426950408889634f

__device__ unsigned int g_ticket;

__global__ void reset_ticket() { g_ticket = 0u; }

__device__ __forceinline__ uint32_t smem_u32(const void* p) {
    uint32_t a;
    asm("{ .reg .u64 t; cvta.to.shared.u64 t, %1; cvt.u32.u64 %0, t; }"
        : "=r"(a) : "l"(p));
    return a;
}

__device__ __forceinline__ float ex2f(float v) {
    float r;
    asm("ex2.approx.f32 %0, %1;" : "=f"(r) : "f"(v));
    return r;
}

__device__ __forceinline__ void ldsm4t(uint32_t& r0, uint32_t& r1,
                                       uint32_t& r2, uint32_t& r3, uint32_t addr) {
    asm volatile("ldmatrix.sync.aligned.m8n8.x4.trans.shared.b16 {%0,%1,%2,%3}, [%4];"
                 : "=r"(r0), "=r"(r1), "=r"(r2), "=r"(r3) : "r"(addr));
}

__device__ __forceinline__ void mma16816(float* d, const uint32_t* a,
                                         uint32_t b0, uint32_t b1) {
    asm volatile("mma.sync.aligned.m16n8k16.row.col.f32.bf16.bf16.f32 "
                 "{%0,%1,%2,%3}, {%4,%5,%6,%7}, {%8,%9}, {%0,%1,%2,%3};"
                 : "+f"(d[0]), "+f"(d[1]), "+f"(d[2]), "+f"(d[3])
                 : "r"(a[0]), "r"(a[1]), "r"(a[2]), "r"(a[3]), "r"(b0), "r"(b1));
}

// one lane pops a stripe ticket; broadcast to the warp
__device__ __forceinline__ unsigned pop_ticket(int lane) {
    unsigned s = 0;
    if (lane == 0) s = atomicAdd(&g_ticket, 1u);
    return __shfl_sync(0xffffffffu, s, 0);
}

__global__ void __launch_bounds__(NTHR, 1)
density_mma(const float* __restrict__ t, const float* __restrict__ x,
            const float* __restrict__ w, const float* __restrict__ bias,
            float* __restrict__ out, int nstripes)
{
    extern __shared__ __align__(128) unsigned char smem[];
    __nv_bfloat16* whi = reinterpret_cast<__nv_bfloat16*>(smem + SM_WHI);
    __nv_bfloat16* wlo = reinterpret_cast<__nv_bfloat16*>(smem + SM_WLO);
    float* bs = reinterpret_cast<float*>(smem + SM_BIAS);   // bias * log2e

    const int tid = threadIdx.x;

    // ---- one-time: stage W as (hi, lo) bf16 with padded pitch + scaled bias ----
    for (int e = tid; e < IND * OUTD; e += NTHR) {
        const int k = e >> 8, n = e & 255;
        const float v = w[e];
        const __nv_bfloat16 h = __float2bfloat16(v);
        whi[k * WPITCH + n] = h;
        wlo[k * WPITCH + n] = __float2bfloat16(v - __bfloat162float(h));
    }
    if (tid < OUTD) bs[tid] = bias[tid] * LOG2E;
    __syncthreads();

    const int lane = tid & 31;
    const int gq   = lane >> 2;   // 0..7: row within stripe half
    const int qid  = lane & 3;    // 0..3: column quad

    const uint32_t whi_u = smem_u32(whi);
    const uint32_t wlo_u = smem_u32(wlo);
    // ldmatrix.trans x4 lane addressing: lanes 0-15 -> k rows at n0, 16-31 -> n0+8
    const uint32_t lrow = (uint32_t)(lane & 15) * (WPITCH * 2);
    const uint32_t lcol = (uint32_t)((lane >> 4) << 3) * 2;

    unsigned s = pop_ticket(lane);

    while (s < (unsigned)nstripes) {
        const int row0  = (int)(s << 4);
        const int row_a = row0 + gq;
        const int row_b = row_a + 8;

        // ---- load A (16 x 128) straight into mma fragments, hi+lo split ----
        uint32_t Ah[8][4], Al[8][4];
        #pragma unroll
        for (int ks = 0; ks < 8; ks++)
            #pragma unroll
            for (int q = 0; q < 2; q++)
                #pragma unroll
                for (int p = 0; p < 2; p++) {
                    const float2 v = *reinterpret_cast<const float2*>(
                        x + (size_t)(row0 + p * 8 + gq) * IND + ks * 16 + qid * 2 + q * 8);
                    const __nv_bfloat162 h = __floats2bfloat162_rn(v.x, v.y);
                    const float2 hf = __bfloat1622float2(h);
                    const __nv_bfloat162 l = __floats2bfloat162_rn(v.x - hf.x, v.y - hf.y);
                    Ah[ks][q * 2 + p] = *reinterpret_cast<const uint32_t*>(&h);
                    Al[ks][q * 2 + p] = *reinterpret_cast<const uint32_t*>(&l);
                }

        // ---- pop next ticket now: ATOMG latency hides under the chunk loop ----
        const unsigned nxt = pop_ticket(lane);

        // ---- per-row grid indices / softmax state ----
        const float ta = __ldg(t + row_a), tb = __ldg(t + row_b);
        const float tga = ta * 255.0f, tgb = tb * 255.0f;
        const float Uaf = ceilf(tga),  Ubf = ceilf(tgb);
        const float intera = 1.0f - (Uaf - tga);
        const float interb = 1.0f - (Ubf - tgb);
        const int Uia = (int)Uaf, Uib = (int)Ubf;
        const int Lia = max(Uia - 1, 0), Lib = max(Uib - 1, 0);

        float sa = 0.f, sb = 0.f, gla = 0.f, glb = 0.f, gua = 0.f, gub = 0.f;

        // ---- 8 column chunks of 32 (rolled loop: small I$ footprint) ----
        for (int c = 0; c < 8; c++) {
            float acc[4][4];
            #pragma unroll
            for (int i = 0; i < 4; i++)
                #pragma unroll
                for (int j = 0; j < 4; j++) acc[i][j] = 0.f;

            const uint32_t cbyte = (uint32_t)(c * 32) * 2 + lrow + lcol;

            #pragma unroll
            for (int ks = 0; ks < 8; ks++) {
                const uint32_t boff = (uint32_t)(ks * 16) * (WPITCH * 2) + cbyte;
                uint32_t h0, h1, h2, h3, h4, h5, h6, h7;
                uint32_t l0, l1, l2, l3, l4, l5, l6, l7;
                ldsm4t(h0, h1, h2, h3, whi_u + boff);
                ldsm4t(h4, h5, h6, h7, whi_u + boff + 32);
                ldsm4t(l0, l1, l2, l3, wlo_u + boff);
                ldsm4t(l4, l5, l6, l7, wlo_u + boff + 32);
                // phase 1: hi*hi (4 independent accs)
                mma16816(acc[0], Ah[ks], h0, h1);
                mma16816(acc[1], Ah[ks], h2, h3);
                mma16816(acc[2], Ah[ks], h4, h5);
                mma16816(acc[3], Ah[ks], h6, h7);
                // phase 2: hi*lo
                mma16816(acc[0], Ah[ks], l0, l1);
                mma16816(acc[1], Ah[ks], l2, l3);
                mma16816(acc[2], Ah[ks], l4, l5);
                mma16816(acc[3], Ah[ks], l6, l7);
                // phase 3: lo*hi
                mma16816(acc[0], Al[ks], h0, h1);
                mma16816(acc[1], Al[ks], h2, h3);
                mma16816(acc[2], Al[ks], h4, h5);
                mma16816(acc[3], Al[ks], h6, h7);
            }

            // ---- chunk epilogue: exp2(acc*log2e + b2) + sum + one-hot gather ----
            #pragma unroll
            for (int nt = 0; nt < 4; nt++) {
                const int col = c * 32 + nt * 8 + qid * 2;
                const float b0 = bs[col], b1 = bs[col + 1];
                const float e0 = ex2f(fmaf(acc[nt][0], LOG2E, b0));
                const float e1 = ex2f(fmaf(acc[nt][1], LOG2E, b1));
                const float e2 = ex2f(fmaf(acc[nt][2], LOG2E, b0));
                const float e3 = ex2f(fmaf(acc[nt][3], LOG2E, b1));
                sa += e0 + e1;
                sb += e2 + e3;
                if (col == Lia)     gla = e0;
                if (col + 1 == Lia) gla = e1;
                if (col == Uia)     gua = e0;
                if (col + 1 == Uia) gua = e1;
                if (col == Lib)     glb = e2;
                if (col + 1 == Lib) glb = e3;
                if (col == Uib)     gub = e2;
                if (col + 1 == Uib) gub = e3;
            }
        }

        // ---- reduce across the 4-thread column quad ----
        #pragma unroll
        for (int d = 1; d < 4; d <<= 1) {
            sa  += __shfl_xor_sync(0xffffffffu, sa,  d);
            sb  += __shfl_xor_sync(0xffffffffu, sb,  d);
            gla += __shfl_xor_sync(0xffffffffu, gla, d);
            gua += __shfl_xor_sync(0xffffffffu, gua, d);
            glb += __shfl_xor_sync(0xffffffffu, glb, d);
            gub += __shfl_xor_sync(0xffffffffu, gub, d);
        }
        if (qid == 0) {
            out[row_a] = __fdividef(gla + (gua - gla) * intera, sa);
            out[row_b] = __fdividef(glb + (gub - glb) * interb, sb);
        }

        s = nxt;
    }
}

extern "C" void kernel_launch(void* const* d_in, const int* in_sizes, int n_in,
                              void* d_out, int out_size)
{
    const float* t    = (const float*)d_in[0];
    const float* x    = (const float*)d_in[1];
    const float* w    = (const float*)d_in[2];
    const float* bias = (const float*)d_in[3];
    float* out        = (float*)d_out;

    const int n        = in_sizes[0];
    const int nstripes = n >> 4;       // 32768

    int dev = 0, smc = 0;
    cudaGetDevice(&dev);
    cudaDeviceGetAttribute(&smc, cudaDevAttrMultiProcessorCount, dev);
    if (smc <= 0) smc = 148;

    cudaFuncSetAttribute(density_mma,
                         cudaFuncAttributeMaxDynamicSharedMemorySize, SM_TOTAL);

    reset_ticket<<<1, 1>>>();
    density_mma<<<smc, NTHR, SM_TOTAL>>>(t, x, w, bias, out, nstripes);
}

// round 13
// speedup vs baseline: 1.2341x; 1.1955x over previous
#include <cuda_runtime.h>
#include <cuda_fp16.h>
#include <cstdint>

// ============================================================================
// Density_Block via fp16 mma.sync m16n8k16, 2-product merged-residual scheme.
// out[i] = lerp of softmax(x[i,:] @ W + b) at data-dependent cols L/U.
// N=524288, IND=128, OUTD=256.
//   D1 = xh*wh (exact products), D2 = (xh+32*xl)*(wl+wh/32)
//   x@w ~= (31/32)*D1 + D2   (error ~2^-16 relative)
// Persistent: W images (wh, wcb) in smem once; 16 warps/SM, 16-row stripes.
// ============================================================================

#define IND    128
#define OUTD   256
#define WPITCH 264      // padded fp16 pitch: 528B row stride -> conflict-free ldmatrix
#define NTHR   512

#define SM_WHI  0
#define SM_WCB  (IND * WPITCH * 2)          // 67584
#define SM_BIAS (2 * IND * WPITCH * 2)      // 135168
#define SM_TOTAL (SM_BIAS + OUTD * 4 + 16)

#define LOG2E 1.4426950408889634f
#define K31_32_LOG2E (0.96875f * 1.4426950408889634f)

__device__ __forceinline__ uint32_t smem_u32(const void* p) {
    uint32_t a;
    asm("{ .reg .u64 t; cvta.to.shared.u64 t, %1; cvt.u32.u64 %0, t; }"
        : "=r"(a) : "l"(p));
    return a;
}

__device__ __forceinline__ float ex2f(float v) {
    float r;
    asm("ex2.approx.f32 %0, %1;" : "=f"(r) : "f"(v));
    return r;
}

__device__ __forceinline__ void ldsm4t(uint32_t& r0, uint32_t& r1,
                                       uint32_t& r2, uint32_t& r3, uint32_t addr) {
    asm volatile("ldmatrix.sync.aligned.m8n8.x4.trans.shared.b16 {%0,%1,%2,%3}, [%4];"
                 : "=r"(r0), "=r"(r1), "=r"(r2), "=r"(r3) : "r"(addr));
}

__device__ __forceinline__ void mma16816(float* d, const uint32_t* a,
                                         uint32_t b0, uint32_t b1) {
    asm volatile("mma.sync.aligned.m16n8k16.row.col.f32.f16.f16.f32 "
                 "{%0,%1,%2,%3}, {%4,%5,%6,%7}, {%8,%9}, {%0,%1,%2,%3};"
                 : "+f"(d[0]), "+f"(d[1]), "+f"(d[2]), "+f"(d[3])
                 : "r"(a[0]), "r"(a[1]), "r"(a[2]), "r"(a[3]), "r"(b0), "r"(b1));
}

__global__ void __launch_bounds__(NTHR, 1)
density_mma(const float* __restrict__ t, const float* __restrict__ x,
            const float* __restrict__ w, const float* __restrict__ bias,
            float* __restrict__ out, int nstripes)
{
    extern __shared__ __align__(128) unsigned char smem[];
    __half* whi = reinterpret_cast<__half*>(smem + SM_WHI);
    __half* wcb = reinterpret_cast<__half*>(smem + SM_WCB);
    float* bs = reinterpret_cast<float*>(smem + SM_BIAS);   // bias * log2e

    const int tid = threadIdx.x;

    // ---- one-time: stage W images (wh, wl + wh/32) + scaled bias ----
    for (int e = tid; e < IND * OUTD; e += NTHR) {
        const int k = e >> 8, n = e & 255;
        const float v = w[e];
        const __half h = __float2half_rn(v);
        const float hf = __half2float(h);
        whi[k * WPITCH + n] = h;
        wcb[k * WPITCH + n] = __float2half_rn((v - hf) + hf * 0.03125f);
    }
    if (tid < OUTD) bs[tid] = bias[tid] * LOG2E;
    __syncthreads();

    const int lane = tid & 31;
    const int gq   = lane >> 2;   // 0..7: row within stripe half
    const int qid  = lane & 3;    // 0..3: column quad
    const int gwarp  = blockIdx.x * (NTHR / 32) + (tid >> 5);
    const int nwarps = gridDim.x * (NTHR / 32);

    const uint32_t whi_u = smem_u32(whi);
    const uint32_t wcb_u = smem_u32(wcb);
    // ldmatrix.trans x4 lane addressing: lanes 0-15 -> k rows at n0, 16-31 -> n0+8
    const uint32_t lrow = (uint32_t)(lane & 15) * (WPITCH * 2);
    const uint32_t lcol = (uint32_t)((lane >> 4) << 3) * 2;

    for (int s = gwarp; s < nstripes; s += nwarps) {
        const int row0  = s << 4;
        const int row_a = row0 + gq;
        const int row_b = row_a + 8;

        // ---- load A (16 x 128) into fragments: A1 = h(x), A2 = h(xh + 32*xl) ----
        uint32_t A1[8][4], A2[8][4];
        #pragma unroll
        for (int ks = 0; ks < 8; ks++)
            #pragma unroll
            for (int q = 0; q < 2; q++)
                #pragma unroll
                for (int p = 0; p < 2; p++) {
                    const float2 v = *reinterpret_cast<const float2*>(
                        x + (size_t)(row0 + p * 8 + gq) * IND + ks * 16 + qid * 2 + q * 8);
                    const __half2 h = __float22half2_rn(v);
                    const float2 hf = __half22float2(h);
                    float2 a2;
                    a2.x = fmaf(32.0f, v.x - hf.x, hf.x);
                    a2.y = fmaf(32.0f, v.y - hf.y, hf.y);
                    const __half2 h2 = __float22half2_rn(a2);
                    A1[ks][q * 2 + p] = *reinterpret_cast<const uint32_t*>(&h);
                    A2[ks][q * 2 + p] = *reinterpret_cast<const uint32_t*>(&h2);
                }

        // ---- per-row grid indices / softmax state ----
        const float ta = __ldg(t + row_a), tb = __ldg(t + row_b);
        const float tga = ta * 255.0f, tgb = tb * 255.0f;
        const float Uaf = ceilf(tga),  Ubf = ceilf(tgb);
        const float intera = 1.0f - (Uaf - tga);
        const float interb = 1.0f - (Ubf - tgb);
        const int Uia = (int)Uaf, Uib = (int)Ubf;
        const int Lia = max(Uia - 1, 0), Lib = max(Uib - 1, 0);

        float sa = 0.f, sb = 0.f, gla = 0.f, glb = 0.f, gua = 0.f, gub = 0.f;

        // ---- 16 column chunks of 16 (rolled loop: small I$ footprint) ----
        for (int c = 0; c < 16; c++) {
            float ac1[2][4], ac2[2][4];
            #pragma unroll
            for (int i = 0; i < 2; i++)
                #pragma unroll
                for (int j = 0; j < 4; j++) { ac1[i][j] = 0.f; ac2[i][j] = 0.f; }

            const uint32_t cbyte = (uint32_t)(c * 16) * 2 + lrow + lcol;

            #pragma unroll
            for (int ks = 0; ks < 8; ks++) {
                const uint32_t boff = (uint32_t)(ks * 16) * (WPITCH * 2) + cbyte;
                uint32_t h0, h1, h2, h3, c0, c1, c2, c3;
                ldsm4t(h0, h1, h2, h3, whi_u + boff);
                ldsm4t(c0, c1, c2, c3, wcb_u + boff);
                mma16816(ac1[0], A1[ks], h0, h1);   // D1 = xh*wh
                mma16816(ac1[1], A1[ks], h2, h3);
                mma16816(ac2[0], A2[ks], c0, c1);   // D2 = (xh+32xl)*(wl+wh/32)
                mma16816(ac2[1], A2[ks], c2, c3);
            }

            // ---- chunk epilogue: logit = 31/32*D1 + D2; exp2 + sum + gather ----
            #pragma unroll
            for (int nt = 0; nt < 2; nt++) {
                const int col = c * 16 + nt * 8 + qid * 2;
                const float b0 = bs[col], b1 = bs[col + 1];
                const float e0 = ex2f(fmaf(ac1[nt][0], K31_32_LOG2E, fmaf(ac2[nt][0], LOG2E, b0)));
                const float e1 = ex2f(fmaf(ac1[nt][1], K31_32_LOG2E, fmaf(ac2[nt][1], LOG2E, b1)));
                const float e2 = ex2f(fmaf(ac1[nt][2], K31_32_LOG2E, fmaf(ac2[nt][2], LOG2E, b0)));
                const float e3 = ex2f(fmaf(ac1[nt][3], K31_32_LOG2E, fmaf(ac2[nt][3], LOG2E, b1)));
                sa += e0 + e1;
                sb += e2 + e3;
                if (col == Lia)     gla = e0;
                if (col + 1 == Lia) gla = e1;
                if (col == Uia)     gua = e0;
                if (col + 1 == Uia) gua = e1;
                if (col == Lib)     glb = e2;
                if (col + 1 == Lib) glb = e3;
                if (col == Uib)     gub = e2;
                if (col + 1 == Uib) gub = e3;
            }
        }

        // ---- reduce across the 4-thread column quad ----
        #pragma unroll
        for (int d = 1; d < 4; d <<= 1) {
            sa  += __shfl_xor_sync(0xffffffffu, sa,  d);
            sb  += __shfl_xor_sync(0xffffffffu, sb,  d);
            gla += __shfl_xor_sync(0xffffffffu, gla, d);
            gua += __shfl_xor_sync(0xffffffffu, gua, d);
            glb += __shfl_xor_sync(0xffffffffu, glb, d);
            gub += __shfl_xor_sync(0xffffffffu, gub, d);
        }
        if (qid == 0) {
            out[row_a] = __fdividef(gla + (gua - gla) * intera, sa);
            out[row_b] = __fdividef(glb + (gub - glb) * interb, sb);
        }
    }
}

extern "C" void kernel_launch(void* const* d_in, const int* in_sizes, int n_in,
                              void* d_out, int out_size)
{
    const float* t    = (const float*)d_in[0];
    const float* x    = (const float*)d_in[1];
    const float* w    = (const float*)d_in[2];
    const float* bias = (const float*)d_in[3];
    float* out        = (float*)d_out;

    const int n        = in_sizes[0];
    const int nstripes = n >> 4;       // 32768

    int dev = 0, smc = 0;
    cudaGetDevice(&dev);
    cudaDeviceGetAttribute(&smc, cudaDevAttrMultiProcessorCount, dev);
    if (smc <= 0) smc = 148;

    cudaFuncSetAttribute(density_mma,
                         cudaFuncAttributeMaxDynamicSharedMemorySize, SM_TOTAL);
    density_mma<<<smc, NTHR, SM_TOTAL>>>(t, x, w, bias, out, nstripes);
}